// round 1
// baseline (speedup 1.0000x reference)
#include <cuda_runtime.h>
#include <cstdint>

#define MDIM 10000
#define NDIM 512
#define KDIM 512

#define BM 128
#define BN 64
#define BK 16
#define TM 8
#define TN 4

// Scratch for ZW = z_drug @ weight  (10000 x 512 fp32 = 20.48 MB)
__device__ float g_ZW[(size_t)MDIM * NDIM];
// Flag: 1 if batch_edges is int64, 0 if int32
__device__ int g_idx64;

// ---------------------------------------------------------------------------
// Detect edge-index dtype. If the buffer holds int64 values in [0,10000),
// every odd 32-bit word (the high half) is zero. For random int32 indices in
// [0,10000) the probability all 128 sampled odd words are zero is ~1e-512.
// ---------------------------------------------------------------------------
__global__ void detect_idx_kernel(const unsigned int* __restrict__ e32) {
    int is64 = 1;
    for (int i = 0; i < 128; i++) {
        if (e32[2 * i + 1] != 0u) { is64 = 0; break; }
    }
    g_idx64 = is64;
}

// ---------------------------------------------------------------------------
// ZW = A(10000x512) @ B(512x512), fp32, tiled shared-memory GEMM.
// 256 threads, BM=128 x BN=64 block tile, TM=8 x TN=4 per-thread micro-tile.
// ---------------------------------------------------------------------------
__global__ __launch_bounds__(256, 2)
void gemm_zw_kernel(const float* __restrict__ A, const float* __restrict__ B) {
    __shared__ float As[BK][BM];        // A tile stored transposed (k-major)
    __shared__ float Bs[BK][BN];

    const int bm = blockIdx.y * BM;
    const int bn = blockIdx.x * BN;
    const int tid = (int)threadIdx.x;
    const int tcol = tid & 15;          // BN/TN = 16 thread-cols
    const int trow = tid >> 4;          // BM/TM = 16 thread-rows

    float acc[TM][TN];
#pragma unroll
    for (int i = 0; i < TM; i++)
#pragma unroll
        for (int j = 0; j < TN; j++) acc[i][j] = 0.0f;

    for (int k0 = 0; k0 < KDIM; k0 += BK) {
        // Load A tile: BM x BK = 2048 floats = 512 float4, 2 per thread.
#pragma unroll
        for (int i = 0; i < 2; i++) {
            int idx = tid * 2 + i;          // 0..511
            int row = idx >> 2;             // BK/4 = 4 float4 per row
            int kc  = (idx & 3) << 2;
            float4 v = make_float4(0.f, 0.f, 0.f, 0.f);
            int grow = bm + row;
            if (grow < MDIM)
                v = *(const float4*)(A + (size_t)grow * KDIM + k0 + kc);
            As[kc + 0][row] = v.x;
            As[kc + 1][row] = v.y;
            As[kc + 2][row] = v.z;
            As[kc + 3][row] = v.w;
        }
        // Load B tile: BK x BN = 1024 floats = 256 float4, 1 per thread.
        {
            int kr = tid >> 4;              // BN/4 = 16 float4 per row
            int c4 = (tid & 15) << 2;
            float4 v = *(const float4*)(B + (size_t)(k0 + kr) * NDIM + bn + c4);
            *(float4*)&Bs[kr][c4] = v;
        }
        __syncthreads();

#pragma unroll
        for (int k = 0; k < BK; k++) {
            float a[TM], b[TN];
#pragma unroll
            for (int i = 0; i < TM; i++) a[i] = As[k][trow * TM + i];
#pragma unroll
            for (int j = 0; j < TN; j++) b[j] = Bs[k][tcol * TN + j];
#pragma unroll
            for (int i = 0; i < TM; i++)
#pragma unroll
                for (int j = 0; j < TN; j++)
                    acc[i][j] = fmaf(a[i], b[j], acc[i][j]);
        }
        __syncthreads();
    }

    // Store (TN=4 -> one float4 per micro-row)
#pragma unroll
    for (int i = 0; i < TM; i++) {
        int grow = bm + trow * TM + i;
        if (grow < MDIM) {
            float4 v = make_float4(acc[i][0], acc[i][1], acc[i][2], acc[i][3]);
            *(float4*)(g_ZW + (size_t)grow * NDIM + bn + tcol * TN) = v;
        }
    }
}

// ---------------------------------------------------------------------------
// Per-edge score: one warp per edge.
//   score = dot(ZW[row_e], Z[col_e]);  out = sigmoid(score)
// 512 floats per vector = 128 float4 = 4 float4 per lane per vector.
// Both tables fit in L2 (20 MB each), so this runs at L2 bandwidth.
// ---------------------------------------------------------------------------
__global__ __launch_bounds__(256)
void edge_score_kernel(const float* __restrict__ Z,
                       const void* __restrict__ edges,
                       float* __restrict__ out, int E) {
    int gw = (int)((blockIdx.x * blockDim.x + threadIdx.x) >> 5);
    int lane = (int)(threadIdx.x & 31);
    if (gw >= E) return;

    int r, c;
    if (g_idx64) {
        const long long* e = (const long long*)edges;
        r = (int)e[gw];
        c = (int)e[(size_t)E + gw];
    } else {
        const int* e = (const int*)edges;
        r = e[gw];
        c = e[(size_t)E + gw];
    }

    const float4* a = (const float4*)(g_ZW + (size_t)r * NDIM);
    const float4* b = (const float4*)(Z    + (size_t)c * NDIM);

    float sum = 0.0f;
#pragma unroll
    for (int i = 0; i < 4; i++) {
        float4 x = a[lane + 32 * i];
        float4 y = b[lane + 32 * i];
        sum += x.x * y.x + x.y * y.y + x.z * y.z + x.w * y.w;
    }
#pragma unroll
    for (int o = 16; o; o >>= 1)
        sum += __shfl_xor_sync(0xFFFFFFFFu, sum, o);

    if (lane == 0) {
        // sigmoid; expf handles large |sum| gracefully (inf -> 0, 0 -> 1)
        out[gw] = 1.0f / (1.0f + expf(-sum));
    }
}

// ---------------------------------------------------------------------------
extern "C" void kernel_launch(void* const* d_in, const int* in_sizes, int n_in,
                              void* d_out, int out_size) {
    const float* z_drug = (const float*)d_in[0];   // [10000, 512] f32
    const float* weight = (const float*)d_in[1];   // [512, 512]   f32
    const void*  edges  = d_in[2];                 // [2, E] int64 or int32
    float* out = (float*)d_out;                    // [E] f32
    const int E = out_size;

    detect_idx_kernel<<<1, 1>>>((const unsigned int*)edges);

    dim3 grid(NDIM / BN, (MDIM + BM - 1) / BM);    // (8, 79)
    gemm_zw_kernel<<<grid, 256>>>(z_drug, weight);

    int blocks = (E + 7) / 8;                      // 8 warps/block, 1 edge/warp
    edge_score_kernel<<<blocks, 256>>>(z_drug, edges, out, E);
}